// round 16
// baseline (speedup 1.0000x reference)
#include <cuda_runtime.h>
#include <cstdint>

// DeepUDI, four single-stream kernels.
//   kA     : w+qw 201MB (cp.async) -> J -> Jq          [merged kJ+kJq]
//   kB     : w+kw 201MB (cp.async) -> v,u,scores,softmax,g,df
//   kGates : Wx+Wn01 335MB -> rdf, xh, z
//   kHc    : Wn2 67MB  -> out

#define NN   2048
#define RR   2
#define KK   32
#define DD   64
#define FF   64
#define DD2  128
#define HPAD 68
#define NT   (NN * RR)

__device__ float Jq_g [NT * DD2];
__device__ float df_g [NT * FF];
__device__ float rdf_g[NT * FF];
__device__ float xh_g [NT * FF];
__device__ float z_g  [NT * FF];

__device__ __forceinline__ float sigm(float v) {
    return 1.f / (1.f + __expf(-v));
}
__device__ __forceinline__ void cp16(void* dst, const void* src) {
    uint32_t d = (uint32_t)__cvta_generic_to_shared(dst);
    asm volatile("cp.async.cg.shared.global [%0], [%1], 16;\n" :: "r"(d), "l"(src));
}
#define CP_COMMIT() asm volatile("cp.async.commit_group;\n" ::: "memory")
#define CP_WAIT0()  asm volatile("cp.async.wait_group 0;\n" ::: "memory")

// ============ kA: J = h@w; Jq = J@qw  (one tile per CTA) ===============
struct ASmem {
    float w [DD * FF];        // 16KB (cp.async)
    float qw[FF * DD2];       // 32KB (cp.async)
    float h [DD];
    float J [FF];
    float part[2][FF];
    float jqp[2][DD2];
};
#define A_SMEM_BYTES ((int)sizeof(ASmem))

__global__ __launch_bounds__(256)
void kA_kernel(const void* __restrict__ x_raw,
               const float* __restrict__ embed,
               const float* __restrict__ w,
               const float* __restrict__ qw)
{
    extern __shared__ __align__(16) char smem_raw[];
    ASmem* S = (ASmem*)smem_raw;

    const int nr  = blockIdx.x;
    const int n   = nr >> 1;
    const int tid = threadIdx.x;

    // front-issue both streams (zero-reg cp.async, one group)
    const float4* wsrc = (const float4*)(w + (long long)nr * (DD * FF));
    #pragma unroll
    for (int j = 0; j < 4; j++)
        cp16(((float4*)S->w) + tid + 256 * j, wsrc + tid + 256 * j);
    const float4* qsrc = (const float4*)(qw + (long long)nr * (FF * DD2));
    #pragma unroll
    for (int j = 0; j < 8; j++)
        cp16(((float4*)S->qw) + tid + 256 * j, qsrc + tid + 256 * j);
    CP_COMMIT();

    // h load (embed + x are L2-hot; per-thread idx64 detect)
    const int idx64 = (((const int*)x_raw)[1] == 0) ? 1 : 0;
    if (tid < DD) {
        long long xn = idx64 ? ((const long long*)x_raw)[n]
                             : (long long)((const int*)x_raw)[n];
        S->h[tid] = embed[xn * DD + tid];
    }
    CP_WAIT0();
    __syncthreads();

    // J[f] = sum_d h[d]*w[d,f] : 2 threads per f (conflict-free lanes)
    if (tid < 128) {
        int f = tid & 63, dh = tid >> 6;
        float a0 = 0.f, a1 = 0.f;
        #pragma unroll
        for (int d = dh * 32; d < dh * 32 + 32; d += 2) {
            a0 += S->h[d]     * S->w[d * FF + f];
            a1 += S->h[d + 1] * S->w[(d + 1) * FF + f];
        }
        S->part[dh][f] = a0 + a1;
    }
    __syncthreads();
    if (tid < 64) S->J[tid] = S->part[0][tid] + S->part[1][tid];
    __syncthreads();

    // Jq[e] = sum_f J[f]*qw[f,e] : (e, f-half) partials
    {
        int e  = tid & 127;
        int fh = tid >> 7;
        float a0 = 0.f, a1 = 0.f;
        #pragma unroll
        for (int f = fh * 32; f < fh * 32 + 32; f += 2) {
            a0 += S->J[f]     * S->qw[f * DD2 + e];
            a1 += S->J[f + 1] * S->qw[(f + 1) * DD2 + e];
        }
        S->jqp[fh][e] = a0 + a1;
    }
    __syncthreads();

    if (tid < 128)
        Jq_g[(long long)nr * DD2 + tid] = S->jqp[0][tid] + S->jqp[1][tid];
}

// ============ kB: v = kw@Jq; u = w@v; scores; softmax; g; df ===========
struct BSmem {
    float w [DD * FF];        // 16KB (cp.async)
    float kw[FF * DD2];       // 32KB (cp.async)
    float hn[KK][HPAD];       // 8.7KB
    float v [FF];
    float u [FF];
    float sc[KK];
    float g [FF];
    int   nb[KK];
};
#define B_SMEM_BYTES ((int)sizeof(BSmem))

__global__ __launch_bounds__(256)
void kB_kernel(const void* __restrict__ x_raw,
               const void* __restrict__ nb_raw,
               const float* __restrict__ embed,
               const float* __restrict__ w,
               const float* __restrict__ kw)
{
    extern __shared__ __align__(16) char smem_raw[];
    BSmem* S = (BSmem*)smem_raw;

    const int nr   = blockIdx.x;
    const int tid  = threadIdx.x;
    const int wp   = tid >> 5;
    const int lane = tid & 31;

    // front-issue both streams via cp.async (48KB, zero regs)
    const float4* wsrc = (const float4*)(w + (long long)nr * (DD * FF));
    #pragma unroll
    for (int j = 0; j < 4; j++)
        cp16(((float4*)S->w) + tid + 256 * j, wsrc + tid + 256 * j);
    const float4* ksrc = (const float4*)(kw + (long long)nr * (FF * DD2));
    #pragma unroll
    for (int j = 0; j < 8; j++)
        cp16(((float4*)S->kw) + tid + 256 * j, ksrc + tid + 256 * j);
    CP_COMMIT();

    // Jq slice (L2-hot scratch)
    float4 qv = __ldg((const float4*)(Jq_g + (long long)nr * DD2) + lane);

    const int idx64 = (((const int*)x_raw)[1] == 0) ? 1 : 0;
    if (tid < KK) {
        long long base = (long long)nr * KK + tid;
        S->nb[tid] = idx64 ? (int)((const long long*)nb_raw)[base]
                           : ((const int*)nb_raw)[base];
    }
    __syncthreads();

    // hn gather: 512 float4 (embed is L2-resident)
    #pragma unroll
    for (int j = 0; j < 2; j++) {
        int i  = tid + 256 * j;
        int kk = i >> 4, dv = i & 15;
        *(float4*)(&S->hn[kk][dv * 4]) =
            *(const float4*)(embed + (long long)S->nb[kk] * DD + dv * 4);
    }
    CP_WAIT0();
    __syncthreads();

    // ---- v[f] = sum_e kw[f,e]*Jq[e] : warp wp owns rows wp*8..+7 -------
    #pragma unroll
    for (int i = 0; i < 8; i++) {
        int f = wp * 8 + i;
        float4 kv = *(const float4*)&S->kw[f * DD2 + lane * 4];
        float p = kv.x*qv.x + kv.y*qv.y + kv.z*qv.z + kv.w*qv.w;
        #pragma unroll
        for (int off = 16; off > 0; off >>= 1)
            p += __shfl_xor_sync(0xffffffffu, p, off);
        if (lane == 0) S->v[f] = p;
    }
    __syncthreads();

    // ---- u[d] = sum_f w[d,f]*v[f] : 8 warps x 8 d's --------------------
    {
        int l16 = lane & 15, half = lane >> 4;
        float4 vv = *(const float4*)&S->v[l16 * 4];
        #pragma unroll
        for (int i = 0; i < 4; i++) {
            int d = wp * 8 + i * 2 + half;
            float4 wr4 = *(const float4*)&S->w[d * FF + l16 * 4];
            float p = wr4.x*vv.x + wr4.y*vv.y + wr4.z*vv.z + wr4.w*vv.w;
            p += __shfl_xor_sync(0xffffffffu, p, 1);
            p += __shfl_xor_sync(0xffffffffu, p, 2);
            p += __shfl_xor_sync(0xffffffffu, p, 4);
            p += __shfl_xor_sync(0xffffffffu, p, 8);
            if (l16 == 0) S->u[d] = p;
        }
    }
    __syncthreads();

    // ---- scores: 8 threads per k, 8 f's each ---------------------------
    {
        int k = tid >> 3, o = tid & 7, fb = o * 8;
        float s0 = 0.f, s1 = 0.f;
        #pragma unroll
        for (int i = 0; i < 8; i += 2) {
            s0 += S->hn[k][fb + i]     * S->u[fb + i];
            s1 += S->hn[k][fb + i + 1] * S->u[fb + i + 1];
        }
        float s = s0 + s1;
        s += __shfl_xor_sync(0xffffffffu, s, 1);
        s += __shfl_xor_sync(0xffffffffu, s, 2);
        s += __shfl_xor_sync(0xffffffffu, s, 4);
        if (o == 0) S->sc[k] = s;
    }
    __syncthreads();

    // ---- softmax over K=32 (warp 0) ------------------------------------
    if (tid < 32) {
        float s = S->sc[lane];
        float m = s;
        #pragma unroll
        for (int off = 16; off > 0; off >>= 1)
            m = fmaxf(m, __shfl_xor_sync(0xffffffffu, m, off));
        float e = __expf(s - m);
        float sum = e;
        #pragma unroll
        for (int off = 16; off > 0; off >>= 1)
            sum += __shfl_xor_sync(0xffffffffu, sum, off);
        S->sc[lane] = e / sum;
    }
    __syncthreads();

    // ---- g[d] = sum_k E[k]*hn[k,d] : 2 threads per d -------------------
    if (tid < 128) {
        int d = tid & 63, kh = tid >> 6;
        float g0 = 0.f, g1 = 0.f;
        #pragma unroll
        for (int kk = kh * 16; kk < kh * 16 + 16; kk += 2) {
            g0 += S->sc[kk]     * S->hn[kk][d];
            g1 += S->sc[kk + 1] * S->hn[kk + 1][d];
        }
        float gg = g0 + g1;
        if (kh == 1) S->g[d] = gg;
        __syncthreads();
        if (kh == 0) S->g[d] += gg;
    } else {
        __syncthreads();
    }
    __syncthreads();

    // ---- df[f] = sum_d g[d]*w[d,f] : 2 threads per f -------------------
    if (tid < 128) {
        int f = tid & 63, dh = tid >> 6;
        float d0 = 0.f, d1 = 0.f;
        #pragma unroll
        for (int d = dh * 32; d < dh * 32 + 32; d += 2) {
            d0 += S->g[d]     * S->w[d * FF + f];
            d1 += S->g[d + 1] * S->w[(d + 1) * FF + f];
        }
        float dd = d0 + d1;
        if (dh == 1) S->u[f] = dd;
        __syncthreads();
        if (dh == 0) df_g[(long long)nr * FF + f] = dd + S->u[f];
    } else {
        __syncthreads();
    }
}

// ============ kGates: 5 matvecs -> rdf, xh, z (unchanged) ==============
__global__ __launch_bounds__(256)
void kGates_kernel(const void* __restrict__ x_raw,
                   const float* __restrict__ embed,
                   const float* __restrict__ Wx,
                   const float* __restrict__ Wn,
                   const float* __restrict__ bx,
                   const float* __restrict__ bn)
{
    __shared__ float h_s[DD];
    __shared__ float df_s[RR][FF];
    __shared__ __align__(16) float part[RR][8][5][FF];
    __shared__ __align__(16) float red[RR][5][FF];
    __shared__ int flags[2];

    const int n   = blockIdx.x;
    const int tid = threadIdx.x;
    const int r   = tid >> 7;
    const int wg  = tid & 127;

    if (tid == 0) {
        const int* xi = (const int*)x_raw;
        int idx64 = (xi[1] == 0) ? 1 : 0;
        flags[0] = idx64;
        flags[1] = idx64 ? (int)((const long long*)x_raw)[n] : xi[n];
    }
    __syncthreads();
    const int xn = flags[1];

    if (tid < DD) h_s[tid] = embed[(long long)xn * DD + tid];
    if (wg < FF)  df_s[r][wg] = df_g[((long long)n * RR + r) * FF + wg];
    __syncthreads();

    const long long nr = (long long)n * RR + r;
    const float* Wxr = Wx + nr * (3 * DD * FF);
    const float* Wnr = Wn + nr * (3 * FF * FF);
    const float* bxr = bx + nr * (3 * FF);
    const float* bnr = bn + nr * (3 * FF);

    const int ds = wg >> 4;
    const int f4 = (wg & 15) * 4;

    float4 a0 = make_float4(0,0,0,0), a1 = a0, a2v = a0, a3 = a0, a4 = a0;
    #pragma unroll
    for (int dd = 0; dd < 8; dd++) {
        int d = ds * 8 + dd;
        float hd  = h_s[d];
        float dfd = df_s[r][d];
        float4 x0 = __ldg((const float4*)(Wxr + (0*DD + d)*FF + f4));
        float4 x1 = __ldg((const float4*)(Wxr + (1*DD + d)*FF + f4));
        float4 x2 = __ldg((const float4*)(Wxr + (2*DD + d)*FF + f4));
        float4 n0 = __ldg((const float4*)(Wnr + (0*FF + d)*FF + f4));
        float4 n1 = __ldg((const float4*)(Wnr + (1*FF + d)*FF + f4));
        a0.x += hd*x0.x;  a0.y += hd*x0.y;  a0.z += hd*x0.z;  a0.w += hd*x0.w;
        a1.x += hd*x1.x;  a1.y += hd*x1.y;  a1.z += hd*x1.z;  a1.w += hd*x1.w;
        a2v.x+= hd*x2.x;  a2v.y+= hd*x2.y;  a2v.z+= hd*x2.z;  a2v.w+= hd*x2.w;
        a3.x += dfd*n0.x; a3.y += dfd*n0.y; a3.z += dfd*n0.z; a3.w += dfd*n0.w;
        a4.x += dfd*n1.x; a4.y += dfd*n1.y; a4.z += dfd*n1.z; a4.w += dfd*n1.w;
    }
    *(float4*)&part[r][ds][0][f4] = a0;
    *(float4*)&part[r][ds][1][f4] = a1;
    *(float4*)&part[r][ds][2][f4] = a2v;
    *(float4*)&part[r][ds][3][f4] = a3;
    *(float4*)&part[r][ds][4][f4] = a4;
    __syncthreads();

    if (wg < 80) {
        int gate = wg >> 4, fgi = wg & 15;
        float4 s = make_float4(0,0,0,0);
        #pragma unroll
        for (int d2 = 0; d2 < 8; d2++) {
            float4 v = *(const float4*)&part[r][d2][gate][fgi * 4];
            s.x += v.x; s.y += v.y; s.z += v.z; s.w += v.w;
        }
        *(float4*)&red[r][gate][fgi * 4] = s;
    }
    __syncthreads();

    if (wg < FF) {
        int f = wg;
        float xr = red[r][0][f] + __ldg(bxr + f);
        float xz = red[r][1][f] + __ldg(bxr + FF + f);
        float xh = red[r][2][f] + __ldg(bxr + 2*FF + f);
        float rg = sigm(xr + red[r][3][f] + __ldg(bnr + f));
        float z  = sigm(xz + red[r][4][f] + __ldg(bnr + FF + f));
        float dff = df_s[r][f];
        rdf_g[nr * FF + f] = rg * dff;
        xh_g [nr * FF + f] = xh;
        z_g  [nr * FF + f] = z;
    }
}

// ============ kHc: c = rdf@Wn2; Hc; combine; out (unchanged) ===========
__global__ __launch_bounds__(256)
void kHc_kernel(const float* __restrict__ Wn,
                const float* __restrict__ bn,
                float* __restrict__ out)
{
    __shared__ float rdf_s[RR][FF];
    __shared__ __align__(16) float part[RR][8][FF];
    __shared__ float gru_s[RR][FF];

    const int n   = blockIdx.x;
    const int tid = threadIdx.x;
    const int r   = tid >> 7;
    const int wg  = tid & 127;
    const int ds  = wg >> 4;
    const int f4  = (wg & 15) * 4;

    const long long nr = (long long)n * RR + r;
    const float* Wn2 = Wn + nr * (3 * FF * FF) + 2 * FF * FF;

    float4 wv[8];
    #pragma unroll
    for (int dd = 0; dd < 8; dd++)
        wv[dd] = __ldg((const float4*)(Wn2 + (ds * 8 + dd) * FF + f4));

    if (wg < FF) rdf_s[r][wg] = rdf_g[nr * FF + wg];
    __syncthreads();

    float4 a = make_float4(0, 0, 0, 0);
    #pragma unroll
    for (int dd = 0; dd < 8; dd++) {
        float rd = rdf_s[r][ds * 8 + dd];
        a.x += rd * wv[dd].x; a.y += rd * wv[dd].y;
        a.z += rd * wv[dd].z; a.w += rd * wv[dd].w;
    }
    *(float4*)&part[r][ds][f4] = a;
    __syncthreads();

    if (wg < FF) {
        float c = 0.f;
        #pragma unroll
        for (int d2 = 0; d2 < 8; d2++) c += part[r][d2][wg];
        float xh  = xh_g[nr * FF + wg];
        float z   = z_g [nr * FF + wg];
        float dff = df_g[nr * FF + wg];
        float hc = tanhf(xh + c + __ldg(bn + nr * (3 * FF) + 2 * FF + wg));
        gru_s[r][wg] = z * dff + (1.f - z) * hc;
    }
    __syncthreads();

    if (tid < FF)
        out[(long long)n * FF + tid] =
            tanhf(0.5f * (gru_s[0][tid] + gru_s[1][tid]));
}

extern "C" void kernel_launch(void* const* d_in, const int* in_sizes, int n_in,
                              void* d_out, int out_size) {
    (void)in_sizes; (void)n_in; (void)out_size;
    cudaFuncSetAttribute(kA_kernel,
                         cudaFuncAttributeMaxDynamicSharedMemorySize,
                         A_SMEM_BYTES);
    cudaFuncSetAttribute(kB_kernel,
                         cudaFuncAttributeMaxDynamicSharedMemorySize,
                         B_SMEM_BYTES);
    kA_kernel<<<NT, 256, A_SMEM_BYTES>>>(
        d_in[0], (const float*)d_in[2],
        (const float*)d_in[3], (const float*)d_in[4]);
    kB_kernel<<<NT, 256, B_SMEM_BYTES>>>(
        d_in[0], d_in[1], (const float*)d_in[2],
        (const float*)d_in[3], (const float*)d_in[5]);
    kGates_kernel<<<NN, 256>>>(
        d_in[0], (const float*)d_in[2],
        (const float*)d_in[6], (const float*)d_in[7],
        (const float*)d_in[8], (const float*)d_in[9]);
    kHc_kernel<<<NN, 256>>>(
        (const float*)d_in[7], (const float*)d_in[9], (float*)d_out);
}

// round 17
// speedup vs baseline: 1.0786x; 1.0786x over previous
#include <cuda_runtime.h>
#include <cstdint>

// DeepUDI, five single-stream kernels. R17 = R15 (best: 153.6us) with ONE
// change: kHc processes 4 tiles/CTA (grid 1024) so each thread front-issues
// 16 independent LDG.128 instead of 8 (gru_kernel's proven MLP recipe).
//   kJ     : w   67MB  -> J
//   kJq    : qw 134MB  -> Jq
//   kB     : w+kw 201MB -> v,u,scores,softmax,g,df
//   kGates : Wx+Wn01 335MB -> rdf, xh, z
//   kHc    : Wn2 67MB  -> out          [4 tiles/CTA]

#define NN   2048
#define RR   2
#define KK   32
#define DD   64
#define FF   64
#define DD2  128
#define HPAD 68
#define NT   (NN * RR)

__device__ float J_g  [NT * FF];
__device__ float Jq_g [NT * DD2];
__device__ float df_g [NT * FF];
__device__ float rdf_g[NT * FF];
__device__ float xh_g [NT * FF];
__device__ float z_g  [NT * FF];

__device__ __forceinline__ float sigm(float v) {
    return 1.f / (1.f + __expf(-v));
}
__device__ __forceinline__ void cp16(void* dst, const void* src) {
    uint32_t d = (uint32_t)__cvta_generic_to_shared(dst);
    asm volatile("cp.async.cg.shared.global [%0], [%1], 16;\n" :: "r"(d), "l"(src));
}
#define CP_COMMIT() asm volatile("cp.async.commit_group;\n" ::: "memory")
#define CP_WAIT0()  asm volatile("cp.async.wait_group 0;\n" ::: "memory")

// ============ kJ: J = h @ w ============================================
__global__ __launch_bounds__(256)
void kJ_kernel(const void* __restrict__ x_raw,
               const float* __restrict__ embed,
               const float* __restrict__ w)
{
    __shared__ float h_s[DD];
    __shared__ __align__(16) float part[RR][8][FF];
    __shared__ int flags[2];

    const int n   = blockIdx.x;
    const int tid = threadIdx.x;
    const int r   = tid >> 7;
    const int wg  = tid & 127;
    const int ds  = wg >> 4;
    const int f4  = (wg & 15) * 4;

    const float* wr = w + ((long long)n * RR + r) * (DD * FF);
    float4 wv[8];
    #pragma unroll
    for (int dd = 0; dd < 8; dd++)
        wv[dd] = __ldg((const float4*)(wr + (ds * 8 + dd) * FF + f4));

    if (tid == 0) {
        const int* xi = (const int*)x_raw;
        int idx64 = (xi[1] == 0) ? 1 : 0;
        flags[0] = idx64;
        flags[1] = idx64 ? (int)((const long long*)x_raw)[n] : xi[n];
    }
    __syncthreads();
    if (tid < DD) h_s[tid] = embed[(long long)flags[1] * DD + tid];
    __syncthreads();

    float4 a = make_float4(0, 0, 0, 0);
    #pragma unroll
    for (int dd = 0; dd < 8; dd++) {
        float hd = h_s[ds * 8 + dd];
        a.x += hd * wv[dd].x; a.y += hd * wv[dd].y;
        a.z += hd * wv[dd].z; a.w += hd * wv[dd].w;
    }
    *(float4*)&part[r][ds][f4] = a;
    __syncthreads();

    if (tid < 128) {
        int rr = tid >> 6, f = tid & 63;
        float s = 0.f;
        #pragma unroll
        for (int d2 = 0; d2 < 8; d2++) s += part[rr][d2][f];
        J_g[((long long)n * RR + rr) * FF + f] = s;
    }
}

// ============ kJq: Jq = J @ qw, 4 tiles/CTA ============================
__global__ __launch_bounds__(256)
void kJq_kernel(const float* __restrict__ qw)
{
    __shared__ float J_s[4][FF];
    __shared__ __align__(16) float part[4][8][DD2];

    const int t0  = blockIdx.x * 4;
    const int tid = threadIdx.x;

    {
        int t = tid >> 6, f = tid & 63;
        J_s[t][f] = J_g[(long long)(t0 + t) * FF + f];
    }
    __syncthreads();

    const int e4 = tid & 31;
    const int fh = tid >> 5;

    float4 a0 = make_float4(0,0,0,0), a1 = a0, a2 = a0, a3 = a0;
    const float4* q0 = (const float4*)(qw + ((long long)(t0+0) * FF + fh*8) * DD2) + e4;
    const float4* q1 = (const float4*)(qw + ((long long)(t0+1) * FF + fh*8) * DD2) + e4;
    const float4* q2 = (const float4*)(qw + ((long long)(t0+2) * FF + fh*8) * DD2) + e4;
    const float4* q3 = (const float4*)(qw + ((long long)(t0+3) * FF + fh*8) * DD2) + e4;

    #pragma unroll
    for (int f = 0; f < 8; f++) {
        int ff = fh * 8 + f;
        float j0 = J_s[0][ff], j1 = J_s[1][ff];
        float j2 = J_s[2][ff], j3 = J_s[3][ff];
        float4 v0 = __ldg(q0 + f * 32);
        float4 v1 = __ldg(q1 + f * 32);
        float4 v2 = __ldg(q2 + f * 32);
        float4 v3 = __ldg(q3 + f * 32);
        a0.x += j0*v0.x; a0.y += j0*v0.y; a0.z += j0*v0.z; a0.w += j0*v0.w;
        a1.x += j1*v1.x; a1.y += j1*v1.y; a1.z += j1*v1.z; a1.w += j1*v1.w;
        a2.x += j2*v2.x; a2.y += j2*v2.y; a2.z += j2*v2.z; a2.w += j2*v2.w;
        a3.x += j3*v3.x; a3.y += j3*v3.y; a3.z += j3*v3.z; a3.w += j3*v3.w;
    }
    *(float4*)&part[0][fh][e4 * 4] = a0;
    *(float4*)&part[1][fh][e4 * 4] = a1;
    *(float4*)&part[2][fh][e4 * 4] = a2;
    *(float4*)&part[3][fh][e4 * 4] = a3;
    __syncthreads();

    if (tid < 128) {
        int t = tid >> 5, e = tid & 31;
        float4 s = make_float4(0,0,0,0);
        #pragma unroll
        for (int h = 0; h < 8; h++) {
            float4 v = *(const float4*)&part[t][h][e * 4];
            s.x += v.x; s.y += v.y; s.z += v.z; s.w += v.w;
        }
        *(float4*)(Jq_g + (long long)(t0 + t) * DD2 + e * 4) = s;
    }
}

// ============ kB: v = kw@Jq; u = w@v; scores; softmax; g; df ===========
// R15 version: w via cp.async, kw in registers (8 LDG.128), 26KB smem.
struct BSmem {
    float w [DD * FF];        // 16KB (cp.async)
    float hn[KK][HPAD];       // 8.7KB
    float v [FF];
    float u [FF];
    float sc[KK];
    float g [FF];
    int   nb[KK];
};
#define B_SMEM_BYTES ((int)sizeof(BSmem))

__global__ __launch_bounds__(256)
void kB_kernel(const void* __restrict__ x_raw,
               const void* __restrict__ nb_raw,
               const float* __restrict__ embed,
               const float* __restrict__ w,
               const float* __restrict__ kw)
{
    extern __shared__ __align__(16) char smem_raw[];
    BSmem* S = (BSmem*)smem_raw;

    const int nr   = blockIdx.x;
    const int tid  = threadIdx.x;
    const int wp   = tid >> 5;
    const int lane = tid & 31;

    const float4* wsrc = (const float4*)(w + (long long)nr * (DD * FF));
    #pragma unroll
    for (int j = 0; j < 4; j++)
        cp16(((float4*)S->w) + tid + 256 * j, wsrc + tid + 256 * j);
    CP_COMMIT();

    const float4* kr = (const float4*)(kw + ((long long)nr * FF + wp * 8) * DD2) + lane;
    float4 kv[8];
    #pragma unroll
    for (int i = 0; i < 8; i++) kv[i] = __ldg(kr + i * 32);

    float4 qv = __ldg((const float4*)(Jq_g + (long long)nr * DD2) + lane);

    const int idx64 = (((const int*)x_raw)[1] == 0) ? 1 : 0;
    if (tid < KK) {
        long long base = (long long)nr * KK + tid;
        S->nb[tid] = idx64 ? (int)((const long long*)nb_raw)[base]
                           : ((const int*)nb_raw)[base];
    }
    __syncthreads();

    #pragma unroll
    for (int j = 0; j < 2; j++) {
        int i  = tid + 256 * j;
        int kk = i >> 4, dv = i & 15;
        *(float4*)(&S->hn[kk][dv * 4]) =
            *(const float4*)(embed + (long long)S->nb[kk] * DD + dv * 4);
    }

    #pragma unroll
    for (int i = 0; i < 8; i++) {
        float p = kv[i].x*qv.x + kv[i].y*qv.y + kv[i].z*qv.z + kv[i].w*qv.w;
        #pragma unroll
        for (int off = 16; off > 0; off >>= 1)
            p += __shfl_xor_sync(0xffffffffu, p, off);
        if (lane == 0) S->v[wp * 8 + i] = p;
    }
    CP_WAIT0();
    __syncthreads();

    {
        int l16 = lane & 15, half = lane >> 4;
        float4 vv = *(const float4*)&S->v[l16 * 4];
        #pragma unroll
        for (int i = 0; i < 4; i++) {
            int d = wp * 8 + i * 2 + half;
            float4 wr4 = *(const float4*)&S->w[d * FF + l16 * 4];
            float p = wr4.x*vv.x + wr4.y*vv.y + wr4.z*vv.z + wr4.w*vv.w;
            p += __shfl_xor_sync(0xffffffffu, p, 1);
            p += __shfl_xor_sync(0xffffffffu, p, 2);
            p += __shfl_xor_sync(0xffffffffu, p, 4);
            p += __shfl_xor_sync(0xffffffffu, p, 8);
            if (l16 == 0) S->u[d] = p;
        }
    }
    __syncthreads();

    {
        int k = tid >> 3, o = tid & 7, fb = o * 8;
        float s0 = 0.f, s1 = 0.f;
        #pragma unroll
        for (int i = 0; i < 8; i += 2) {
            s0 += S->hn[k][fb + i]     * S->u[fb + i];
            s1 += S->hn[k][fb + i + 1] * S->u[fb + i + 1];
        }
        float s = s0 + s1;
        s += __shfl_xor_sync(0xffffffffu, s, 1);
        s += __shfl_xor_sync(0xffffffffu, s, 2);
        s += __shfl_xor_sync(0xffffffffu, s, 4);
        if (o == 0) S->sc[k] = s;
    }
    __syncthreads();

    if (tid < 32) {
        float s = S->sc[lane];
        float m = s;
        #pragma unroll
        for (int off = 16; off > 0; off >>= 1)
            m = fmaxf(m, __shfl_xor_sync(0xffffffffu, m, off));
        float e = __expf(s - m);
        float sum = e;
        #pragma unroll
        for (int off = 16; off > 0; off >>= 1)
            sum += __shfl_xor_sync(0xffffffffu, sum, off);
        S->sc[lane] = e / sum;
    }
    __syncthreads();

    if (tid < 128) {
        int d = tid & 63, kh = tid >> 6;
        float g0 = 0.f, g1 = 0.f;
        #pragma unroll
        for (int kk = kh * 16; kk < kh * 16 + 16; kk += 2) {
            g0 += S->sc[kk]     * S->hn[kk][d];
            g1 += S->sc[kk + 1] * S->hn[kk + 1][d];
        }
        float gg = g0 + g1;
        if (kh == 1) S->g[d] = gg;
        __syncthreads();
        if (kh == 0) S->g[d] += gg;
    } else {
        __syncthreads();
    }
    __syncthreads();

    if (tid < 128) {
        int f = tid & 63, dh = tid >> 6;
        float d0 = 0.f, d1 = 0.f;
        #pragma unroll
        for (int d = dh * 32; d < dh * 32 + 32; d += 2) {
            d0 += S->g[d]     * S->w[d * FF + f];
            d1 += S->g[d + 1] * S->w[(d + 1) * FF + f];
        }
        float dd = d0 + d1;
        if (dh == 1) S->u[f] = dd;
        __syncthreads();
        if (dh == 0) df_g[(long long)nr * FF + f] = dd + S->u[f];
    } else {
        __syncthreads();
    }
}

// ============ kGates: 5 matvecs -> rdf, xh, z ==========================
__global__ __launch_bounds__(256)
void kGates_kernel(const void* __restrict__ x_raw,
                   const float* __restrict__ embed,
                   const float* __restrict__ Wx,
                   const float* __restrict__ Wn,
                   const float* __restrict__ bx,
                   const float* __restrict__ bn)
{
    __shared__ float h_s[DD];
    __shared__ float df_s[RR][FF];
    __shared__ __align__(16) float part[RR][8][5][FF];
    __shared__ __align__(16) float red[RR][5][FF];
    __shared__ int flags[2];

    const int n   = blockIdx.x;
    const int tid = threadIdx.x;
    const int r   = tid >> 7;
    const int wg  = tid & 127;

    if (tid == 0) {
        const int* xi = (const int*)x_raw;
        int idx64 = (xi[1] == 0) ? 1 : 0;
        flags[0] = idx64;
        flags[1] = idx64 ? (int)((const long long*)x_raw)[n] : xi[n];
    }
    __syncthreads();
    const int xn = flags[1];

    if (tid < DD) h_s[tid] = embed[(long long)xn * DD + tid];
    if (wg < FF)  df_s[r][wg] = df_g[((long long)n * RR + r) * FF + wg];
    __syncthreads();

    const long long nr = (long long)n * RR + r;
    const float* Wxr = Wx + nr * (3 * DD * FF);
    const float* Wnr = Wn + nr * (3 * FF * FF);
    const float* bxr = bx + nr * (3 * FF);
    const float* bnr = bn + nr * (3 * FF);

    const int ds = wg >> 4;
    const int f4 = (wg & 15) * 4;

    float4 a0 = make_float4(0,0,0,0), a1 = a0, a2v = a0, a3 = a0, a4 = a0;
    #pragma unroll
    for (int dd = 0; dd < 8; dd++) {
        int d = ds * 8 + dd;
        float hd  = h_s[d];
        float dfd = df_s[r][d];
        float4 x0 = __ldg((const float4*)(Wxr + (0*DD + d)*FF + f4));
        float4 x1 = __ldg((const float4*)(Wxr + (1*DD + d)*FF + f4));
        float4 x2 = __ldg((const float4*)(Wxr + (2*DD + d)*FF + f4));
        float4 n0 = __ldg((const float4*)(Wnr + (0*FF + d)*FF + f4));
        float4 n1 = __ldg((const float4*)(Wnr + (1*FF + d)*FF + f4));
        a0.x += hd*x0.x;  a0.y += hd*x0.y;  a0.z += hd*x0.z;  a0.w += hd*x0.w;
        a1.x += hd*x1.x;  a1.y += hd*x1.y;  a1.z += hd*x1.z;  a1.w += hd*x1.w;
        a2v.x+= hd*x2.x;  a2v.y+= hd*x2.y;  a2v.z+= hd*x2.z;  a2v.w+= hd*x2.w;
        a3.x += dfd*n0.x; a3.y += dfd*n0.y; a3.z += dfd*n0.z; a3.w += dfd*n0.w;
        a4.x += dfd*n1.x; a4.y += dfd*n1.y; a4.z += dfd*n1.z; a4.w += dfd*n1.w;
    }
    *(float4*)&part[r][ds][0][f4] = a0;
    *(float4*)&part[r][ds][1][f4] = a1;
    *(float4*)&part[r][ds][2][f4] = a2v;
    *(float4*)&part[r][ds][3][f4] = a3;
    *(float4*)&part[r][ds][4][f4] = a4;
    __syncthreads();

    if (wg < 80) {
        int gate = wg >> 4, fgi = wg & 15;
        float4 s = make_float4(0,0,0,0);
        #pragma unroll
        for (int d2 = 0; d2 < 8; d2++) {
            float4 v = *(const float4*)&part[r][d2][gate][fgi * 4];
            s.x += v.x; s.y += v.y; s.z += v.z; s.w += v.w;
        }
        *(float4*)&red[r][gate][fgi * 4] = s;
    }
    __syncthreads();

    if (wg < FF) {
        int f = wg;
        float xr = red[r][0][f] + __ldg(bxr + f);
        float xz = red[r][1][f] + __ldg(bxr + FF + f);
        float xh = red[r][2][f] + __ldg(bxr + 2*FF + f);
        float rg = sigm(xr + red[r][3][f] + __ldg(bnr + f));
        float z  = sigm(xz + red[r][4][f] + __ldg(bnr + FF + f));
        float dff = df_s[r][f];
        rdf_g[nr * FF + f] = rg * dff;
        xh_g [nr * FF + f] = xh;
        z_g  [nr * FF + f] = z;
    }
}

// ============ kHc: 4 tiles/CTA (2 nodes), 16 LDG.128/thread ============
__global__ __launch_bounds__(256)
void kHc_kernel(const float* __restrict__ Wn,
                const float* __restrict__ bn,
                float* __restrict__ out)
{
    __shared__ float rdf_s[4][FF];
    __shared__ __align__(16) float part[4][8][FF];   // 8KB
    __shared__ float gru_s[4][FF];

    const int bid = blockIdx.x;            // 1024 CTAs, 2 nodes each
    const int tid = threadIdx.x;
    const int tin = tid >> 7;              // 0/1: this thread's tile pair
    const int wg  = tid & 127;
    const int ds  = wg >> 4;
    const int f4  = (wg & 15) * 4;
    const int tA  = tin;                   // local tiles {tin, tin+2}
    const int tB  = tin + 2;
    const long long nrA = (long long)bid * 4 + tA;
    const long long nrB = (long long)bid * 4 + tB;

    // front-issue Wn2 for both tiles: 16 independent LDG.128
    const float* WnA = Wn + nrA * (3 * FF * FF) + 2 * FF * FF;
    const float* WnB = Wn + nrB * (3 * FF * FF) + 2 * FF * FF;
    float4 wA[8], wB[8];
    #pragma unroll
    for (int dd = 0; dd < 8; dd++) {
        wA[dd] = __ldg((const float4*)(WnA + (ds * 8 + dd) * FF + f4));
        wB[dd] = __ldg((const float4*)(WnB + (ds * 8 + dd) * FF + f4));
    }

    // rdf for all 4 tiles: 256 floats, one per thread
    {
        int t = tid >> 6, f = tid & 63;
        rdf_s[t][f] = rdf_g[((long long)bid * 4 + t) * FF + f];
    }
    __syncthreads();

    float4 aA = make_float4(0,0,0,0), aB = aA;
    #pragma unroll
    for (int dd = 0; dd < 8; dd++) {
        int d = ds * 8 + dd;
        float rA = rdf_s[tA][d];
        float rB = rdf_s[tB][d];
        aA.x += rA * wA[dd].x; aA.y += rA * wA[dd].y;
        aA.z += rA * wA[dd].z; aA.w += rA * wA[dd].w;
        aB.x += rB * wB[dd].x; aB.y += rB * wB[dd].y;
        aB.z += rB * wB[dd].z; aB.w += rB * wB[dd].w;
    }
    *(float4*)&part[tA][ds][f4] = aA;
    *(float4*)&part[tB][ds][f4] = aB;
    __syncthreads();

    // reduce + gate tail: 256 threads = 4 tiles x 64 f
    {
        int t = tid >> 6, f = tid & 63;
        long long nr = (long long)bid * 4 + t;
        float c = 0.f;
        #pragma unroll
        for (int d2 = 0; d2 < 8; d2++) c += part[t][d2][f];
        float xh  = xh_g[nr * FF + f];
        float z   = z_g [nr * FF + f];
        float dff = df_g[nr * FF + f];
        float hc = tanhf(xh + c + __ldg(bn + nr * (3 * FF) + 2 * FF + f));
        gru_s[t][f] = z * dff + (1.f - z) * hc;
    }
    __syncthreads();

    // combine: 2 nodes x 64 f; node 0 -> tiles {0,1}, node 1 -> {2,3}
    if (tid < 128) {
        int node = tid >> 6, f = tid & 63;
        out[((long long)bid * 2 + node) * FF + f] =
            tanhf(0.5f * (gru_s[2 * node][f] + gru_s[2 * node + 1][f]));
    }
}

extern "C" void kernel_launch(void* const* d_in, const int* in_sizes, int n_in,
                              void* d_out, int out_size) {
    (void)in_sizes; (void)n_in; (void)out_size;
    cudaFuncSetAttribute(kB_kernel,
                         cudaFuncAttributeMaxDynamicSharedMemorySize,
                         B_SMEM_BYTES);
    kJ_kernel<<<NN, 256>>>(
        d_in[0], (const float*)d_in[2], (const float*)d_in[3]);
    kJq_kernel<<<NT / 4, 256>>>((const float*)d_in[4]);
    kB_kernel<<<NT, 256, B_SMEM_BYTES>>>(
        d_in[0], d_in[1], (const float*)d_in[2],
        (const float*)d_in[3], (const float*)d_in[5]);
    kGates_kernel<<<NN, 256>>>(
        d_in[0], (const float*)d_in[2],
        (const float*)d_in[6], (const float*)d_in[7],
        (const float*)d_in[8], (const float*)d_in[9]);
    kHc_kernel<<<NN / 2, 256>>>(
        (const float*)d_in[7], (const float*)d_in[9], (float*)d_out);
}